// round 12
// baseline (speedup 1.0000x reference)
#include <cuda_runtime.h>
#include <cuda_bf16.h>

#define NODE_DIM 64
#define EDGE_DIM 32
#define HIDDEN   128
#define MAXN     100000
#define MAXE     800000
#define LN_EPS   1e-5f

typedef unsigned long long u64;

// ---------------- scratch (no allocs allowed) ----------------
__device__ __align__(16) float g_xs[MAXN * HIDDEN];   // x @ W_src
__device__ __align__(16) float g_xd[MAXN * HIDDEN];   // x @ W_dst + b_msg1
__device__ __align__(16) float g_S [MAXN * HIDDEN];   // scatter-sum of edge activations
__device__ __align__(16) float g_eaW[(size_t)MAXE * HIDDEN]; // ea @ W_edge  (410 MB)
__device__ __align__(16) float g_deg[MAXN];           // in-degree (float)
__device__ __align__(16) float g_c [HIDDEN];          // b_msg2 @ W_upd1[64:192]
__device__ __align__(16) float g_Wf_p[64 * 128 * 2];  // conflict-free pair layout

// ---------------- helpers ----------------
__device__ __forceinline__ u64 pk(float lo, float hi) {
    u64 r; asm("mov.b64 %0,{%1,%2};" : "=l"(r) : "f"(lo), "f"(hi)); return r;
}
__device__ __forceinline__ void fma2(u64& d, u64 a, u64 b) {
    asm("fma.rn.f32x2 %0,%1,%2,%0;" : "+l"(d) : "l"(a), "l"(b));
}
__device__ __forceinline__ float psum(u64 v) {
    float lo, hi; asm("mov.b64 {%0,%1},%2;" : "=f"(lo), "=f"(hi) : "l"(v));
    return lo + hi;
}
__device__ __forceinline__ float silu_f(float y) {
    return y * (1.0f / (1.0f + __expf(-y)));
}
__device__ __forceinline__ void red_add_v4(float* p, float4 v) {
    asm volatile("red.global.add.v4.f32 [%0], {%1,%2,%3,%4};"
                 :: "l"(p), "f"(v.x), "f"(v.y), "f"(v.z), "f"(v.w) : "memory");
}

// conflict-free pair layout index: W[k][c] -> base[((kp*4+cc)*32 + lane)*2 + h]
__device__ __forceinline__ int pidx(int k, int c) {
    return (((k >> 1) * 4 + (c & 3)) * 32 + (c >> 2)) * 2 + (k & 1);
}

// ---------------- K fuse: Wf = W_msg2 @ W_upd1[64:192] ----------
__global__ void k_fuse(const float* __restrict__ Wmsg2,
                       const float* __restrict__ Wupd1,
                       const float* __restrict__ bmsg2) {
    int k = blockIdx.x;      // 0..127
    int t = threadIdx.x;     // 0..127
    float acc = 0.f;
#pragma unroll 8
    for (int j = 0; j < HIDDEN; ++j)
        acc = fmaf(Wmsg2[k * HIDDEN + j], Wupd1[(NODE_DIM + j) * HIDDEN + t], acc);
    g_Wf_p[pidx(k, t)] = acc;
    if (k == 0) {
        float c = 0.f;
#pragma unroll 8
        for (int j = 0; j < HIDDEN; ++j)
            c = fmaf(bmsg2[j], Wupd1[(NODE_DIM + j) * HIDDEN + t], c);
        g_c[t] = c;
    }
}

// ---------------- K node_proj: xs = x@W_src, xd = x@W_dst + b1 (FFMA2) ----------
__global__ __launch_bounds__(256)
void k_node_proj(const float* __restrict__ x,
                 const float* __restrict__ Wmsg1,
                 const float* __restrict__ b1, int N) {
    extern __shared__ float sm[];
    float* sWs = sm;             // 8192 (pair layout)
    float* sWd = sWs + 8192;     // 8192
    float* sX  = sWd + 8192;     // 8 warps * 4 nodes * 64 = 2048
    for (int i = threadIdx.x; i < 8192; i += blockDim.x) {
        const int k = i >> 7, c = i & 127;
        const int idx = pidx(k, c);
        sWs[idx] = Wmsg1[i];
        sWd[idx] = Wmsg1[8192 + i];
    }
    __syncthreads();
    const int lane = threadIdx.x & 31, warp = threadIdx.x >> 5;
    const int gw = blockIdx.x * 8 + warp;
    const int nwarps = gridDim.x * 8;
    float* myX = &sX[warp * 4 * 64];
    const float4 b1v = *(const float4*)&b1[lane * 4];

    for (int base = gw * 4; base < N; base += nwarps * 4) {
        __syncwarp();
#pragma unroll
        for (int j = 0; j < 4; ++j) {
            const int n = base + j;
            float2 xv = make_float2(0.f, 0.f);
            if (n < N) xv = *(const float2*)&x[n * NODE_DIM + lane * 2];
            *(float2*)&myX[j * 64 + lane * 2] = xv;
        }
        __syncwarp();
        u64 aS[4][4], aD[4][4];
#pragma unroll
        for (int j = 0; j < 4; ++j)
#pragma unroll
            for (int cc = 0; cc < 4; ++cc) { aS[j][cc] = 0ull; aD[j][cc] = 0ull; }
#pragma unroll
        for (int kp = 0; kp < 32; ++kp) {
            u64 ws[4], wd[4];
#pragma unroll
            for (int cc = 0; cc < 4; ++cc) {
                ws[cc] = *(const u64*)&sWs[((kp * 4 + cc) * 32 + lane) * 2];
                wd[cc] = *(const u64*)&sWd[((kp * 4 + cc) * 32 + lane) * 2];
            }
#pragma unroll
            for (int j = 0; j < 4; ++j) {
                const u64 a = *(const u64*)&myX[j * 64 + kp * 2];
                fma2(aS[j][0], a, ws[0]); fma2(aS[j][1], a, ws[1]);
                fma2(aS[j][2], a, ws[2]); fma2(aS[j][3], a, ws[3]);
                fma2(aD[j][0], a, wd[0]); fma2(aD[j][1], a, wd[1]);
                fma2(aD[j][2], a, wd[2]); fma2(aD[j][3], a, wd[3]);
            }
        }
#pragma unroll
        for (int j = 0; j < 4; ++j) {
            const int n = base + j;
            if (n < N) {
                float4 os = make_float4(psum(aS[j][0]), psum(aS[j][1]),
                                        psum(aS[j][2]), psum(aS[j][3]));
                float4 od = make_float4(psum(aD[j][0]) + b1v.x, psum(aD[j][1]) + b1v.y,
                                        psum(aD[j][2]) + b1v.z, psum(aD[j][3]) + b1v.w);
                *(float4*)&g_xs[(size_t)n * HIDDEN + lane * 4] = os;
                *(float4*)&g_xd[(size_t)n * HIDDEN + lane * 4] = od;
            }
        }
    }
}

// ---------------- K eaw: g_eaW = ea @ W_edge (coalesced GEMM, FFMA2) ----------
__global__ __launch_bounds__(256)
void k_eaw(const float* __restrict__ ea, const float* __restrict__ Wmsg1, int E) {
    __shared__ __align__(16) float sWe[16 * 4 * 32 * 2]; // 4096, pair layout
    __shared__ __align__(16) float sE[8 * 4 * 32];       // staged ea per warp
    for (int i = threadIdx.x; i < EDGE_DIM * HIDDEN; i += blockDim.x) {
        const int k = i >> 7, c = i & 127;
        sWe[pidx(k, c)] = Wmsg1[HIDDEN * HIDDEN + i];
    }
    __syncthreads();
    const int lane = threadIdx.x & 31, warp = threadIdx.x >> 5;
    const int gw = blockIdx.x * 8 + warp;
    const int nwarps = gridDim.x * 8;
    float* myE = &sE[warp * 128];

    for (int base = gw * 4; base < E; base += nwarps * 4) {
        __syncwarp();
#pragma unroll
        for (int j = 0; j < 4; ++j) {
            const int e = base + j;
            myE[j * 32 + lane] = (e < E) ? ea[(size_t)e * EDGE_DIM + lane] : 0.f;
        }
        __syncwarp();
        u64 acc[4][4];
#pragma unroll
        for (int j = 0; j < 4; ++j)
#pragma unroll
            for (int cc = 0; cc < 4; ++cc) acc[j][cc] = 0ull;
#pragma unroll
        for (int kp = 0; kp < 16; ++kp) {
            u64 w[4];
#pragma unroll
            for (int cc = 0; cc < 4; ++cc)
                w[cc] = *(const u64*)&sWe[((kp * 4 + cc) * 32 + lane) * 2];
#pragma unroll
            for (int j = 0; j < 4; ++j) {
                const u64 a = *(const u64*)&myE[j * 32 + kp * 2];  // broadcast
                fma2(acc[j][0], a, w[0]); fma2(acc[j][1], a, w[1]);
                fma2(acc[j][2], a, w[2]); fma2(acc[j][3], a, w[3]);
            }
        }
#pragma unroll
        for (int j = 0; j < 4; ++j) {
            const int e = base + j;
            if (e < E) {
                float4 o = make_float4(psum(acc[j][0]), psum(acc[j][1]),
                                       psum(acc[j][2]), psum(acc[j][3]));
                *(float4*)&g_eaW[(size_t)e * HIDDEN + lane * 4] = o;
            }
        }
    }
}

// ---------------- K edge_lite: gather + sum + LN + SiLU + scatter ------
__global__ __launch_bounds__(256)
void k_edge_lite(const int* __restrict__ ei,
                 const float* __restrict__ gm, const float* __restrict__ bem, int E) {
    __shared__ __align__(16) float sg[HIDDEN];
    __shared__ __align__(16) float sbe[HIDDEN];
    for (int i = threadIdx.x; i < HIDDEN; i += blockDim.x) {
        sg[i] = gm[i]; sbe[i] = bem[i];
    }
    __syncthreads();
    const int lane = threadIdx.x & 31, warp = threadIdx.x >> 5;
    const int gw = blockIdx.x * 8 + warp;
    const int nwarps = gridDim.x * 8;
    const float4 gv  = *(const float4*)&sg[lane * 4];
    const float4 bev = *(const float4*)&sbe[lane * 4];

    for (int base = gw * 4; base < E; base += nwarps * 4) {
        int dsts[4];
        float4 acc[4];
#pragma unroll
        for (int j = 0; j < 4; ++j) {
            const int e = base + j;
            if (e < E) {
                const int src = ei[e];
                dsts[j] = ei[E + e];
                const float4 vs = *(const float4*)&g_xs[(size_t)src * HIDDEN + lane * 4];
                const float4 vd = *(const float4*)&g_xd[(size_t)dsts[j] * HIDDEN + lane * 4];
                const float4 ve = *(const float4*)&g_eaW[(size_t)e * HIDDEN + lane * 4];
                acc[j].x = vs.x + vd.x + ve.x;
                acc[j].y = vs.y + vd.y + ve.y;
                acc[j].z = vs.z + vd.z + ve.z;
                acc[j].w = vs.w + vd.w + ve.w;
            } else {
                dsts[j] = -1;
                acc[j] = make_float4(0.f, 0.f, 0.f, 0.f);
            }
        }
#pragma unroll
        for (int j = 0; j < 4; ++j) {
            if (dsts[j] < 0) continue;
            float s1 = acc[j].x + acc[j].y + acc[j].z + acc[j].w;
            float s2 = fmaf(acc[j].x, acc[j].x, fmaf(acc[j].y, acc[j].y,
                       fmaf(acc[j].z, acc[j].z, acc[j].w * acc[j].w)));
#pragma unroll
            for (int o = 16; o > 0; o >>= 1) {
                s1 += __shfl_xor_sync(0xffffffffu, s1, o);
                s2 += __shfl_xor_sync(0xffffffffu, s2, o);
            }
            const float mu = s1 * (1.0f / HIDDEN);
            const float var = fmaf(-mu, mu, s2 * (1.0f / HIDDEN));
            const float rstd = rsqrtf(var + LN_EPS);
            float4 act;
            act.x = silu_f((acc[j].x - mu) * rstd * gv.x + bev.x);
            act.y = silu_f((acc[j].y - mu) * rstd * gv.y + bev.y);
            act.z = silu_f((acc[j].z - mu) * rstd * gv.z + bev.z);
            act.w = silu_f((acc[j].w - mu) * rstd * gv.w + bev.w);
            red_add_v4(&g_S[(size_t)dsts[j] * HIDDEN + lane * 4], act);
            if (lane == 0) atomicAdd(&g_deg[dsts[j]], 1.0f);
        }
    }
}

// ---------------- K update: fused node update (512 thr, warp per 2 nodes, FFMA2) ------
__global__ __launch_bounds__(512, 1)
void k_update(const float* __restrict__ x,
              const float* __restrict__ Wupd1, const float* __restrict__ bupd1,
              const float* __restrict__ gu, const float* __restrict__ beu,
              const float* __restrict__ Wupd2, const float* __restrict__ bupd2,
              float* __restrict__ out, int N) {
    extern __shared__ float sm[];
    float* sWa = sm;                       // 8192  (pair layout)
    float* sWf = sWa + 8192;               // 16384 (pair layout)
    float* sW2 = sWf + 16384;              // 8192  (interleave, conflict-free)
    float* sb1 = sW2 + 8192;               // 128
    float* sc  = sb1 + HIDDEN;             // 128
    float* sg  = sc  + HIDDEN;             // 128
    float* sbe = sg  + HIDDEN;             // 128
    float* sb2 = sbe + HIDDEN;             // 64
    float* sT  = sb2 + NODE_DIM;           // 16 warps * 2 nodes * 192 = 6144
    for (int i = threadIdx.x; i < 8192; i += blockDim.x) {
        const int k = i >> 7, c = i & 127;
        sWa[pidx(k, c)] = Wupd1[i];
        const int k2 = i >> 6, c2 = i & 63;
        sW2[(k2 >> 1) * 128 + c2 * 2 + (k2 & 1)] = Wupd2[i];
    }
    {
        float4* d = (float4*)sWf; const float4* s = (const float4*)g_Wf_p;
        for (int i = threadIdx.x; i < 4096; i += blockDim.x) d[i] = s[i];
    }
    for (int i = threadIdx.x; i < HIDDEN; i += blockDim.x) {
        sb1[i] = bupd1[i]; sc[i] = g_c[i]; sg[i] = gu[i]; sbe[i] = beu[i];
    }
    for (int i = threadIdx.x; i < NODE_DIM; i += blockDim.x) sb2[i] = bupd2[i];
    __syncthreads();

    const int lane = threadIdx.x & 31, warp = threadIdx.x >> 5;
    const int gw = blockIdx.x * 16 + warp;
    const int nwarps = gridDim.x * 16;
    float* myT = &sT[warp * 2 * 192];   // per node: [0..63]=x, [64..191]=S then act

    const float4 b1v = *(const float4*)&sb1[lane * 4];
    const float4 cv  = *(const float4*)&sc [lane * 4];
    const float4 gv  = *(const float4*)&sg [lane * 4];
    const float4 bev = *(const float4*)&sbe[lane * 4];
    const float2 b2v = *(const float2*)&sb2[lane * 2];

    for (int base = gw * 2; base < N; base += nwarps * 2) {
        __syncwarp();
        u64 acc[2][4];
#pragma unroll
        for (int j = 0; j < 2; ++j) {
            const int n = base + j;
            float2 xv = make_float2(0.f, 0.f);
            float4 s4 = make_float4(0.f, 0.f, 0.f, 0.f);
            float dg = 0.f;
            if (n < N) {
                xv = *(const float2*)&x[n * NODE_DIM + lane * 2];
                s4 = *(const float4*)&g_S[(size_t)n * HIDDEN + lane * 4];
                dg = g_deg[n];
            }
            *(float2*)&myT[j * 192 + lane * 2] = xv;
            *(float4*)&myT[j * 192 + 64 + lane * 4] = s4;
            acc[j][0] = pk(fmaf(dg, cv.x, b1v.x), 0.f);
            acc[j][1] = pk(fmaf(dg, cv.y, b1v.y), 0.f);
            acc[j][2] = pk(fmaf(dg, cv.z, b1v.z), 0.f);
            acc[j][3] = pk(fmaf(dg, cv.w, b1v.w), 0.f);
        }
        __syncwarp();
        // loop1: x @ W_upd1[0:64]
#pragma unroll
        for (int kp = 0; kp < 32; ++kp) {
            u64 w[4];
#pragma unroll
            for (int cc = 0; cc < 4; ++cc)
                w[cc] = *(const u64*)&sWa[((kp * 4 + cc) * 32 + lane) * 2];
#pragma unroll
            for (int j = 0; j < 2; ++j) {
                const u64 a = *(const u64*)&myT[j * 192 + kp * 2];
                fma2(acc[j][0], a, w[0]); fma2(acc[j][1], a, w[1]);
                fma2(acc[j][2], a, w[2]); fma2(acc[j][3], a, w[3]);
            }
        }
        // loop2: S @ Wf
#pragma unroll
        for (int kp = 0; kp < 64; ++kp) {
            u64 w[4];
#pragma unroll
            for (int cc = 0; cc < 4; ++cc)
                w[cc] = *(const u64*)&sWf[((kp * 4 + cc) * 32 + lane) * 2];
#pragma unroll
            for (int j = 0; j < 2; ++j) {
                const u64 a = *(const u64*)&myT[j * 192 + 64 + kp * 2];
                fma2(acc[j][0], a, w[0]); fma2(acc[j][1], a, w[1]);
                fma2(acc[j][2], a, w[2]); fma2(acc[j][3], a, w[3]);
            }
        }
        __syncwarp();
        // LayerNorm (one pass) + SiLU, store act into the S slots
#pragma unroll
        for (int j = 0; j < 2; ++j) {
            const float v0 = psum(acc[j][0]), v1 = psum(acc[j][1]);
            const float v2 = psum(acc[j][2]), v3 = psum(acc[j][3]);
            float s1 = v0 + v1 + v2 + v3;
            float s2 = fmaf(v0, v0, fmaf(v1, v1, fmaf(v2, v2, v3 * v3)));
#pragma unroll
            for (int o = 16; o > 0; o >>= 1) {
                s1 += __shfl_xor_sync(0xffffffffu, s1, o);
                s2 += __shfl_xor_sync(0xffffffffu, s2, o);
            }
            const float mu = s1 * (1.0f / HIDDEN);
            const float var = fmaf(-mu, mu, s2 * (1.0f / HIDDEN));
            const float rstd = rsqrtf(var + LN_EPS);
            float4 act;
            act.x = silu_f((v0 - mu) * rstd * gv.x + bev.x);
            act.y = silu_f((v1 - mu) * rstd * gv.y + bev.y);
            act.z = silu_f((v2 - mu) * rstd * gv.z + bev.z);
            act.w = silu_f((v3 - mu) * rstd * gv.w + bev.w);
            *(float4*)&myT[j * 192 + 64 + lane * 4] = act;
        }
        __syncwarp();
        // loop3: act @ W_upd2 (128 -> 64)
        u64 o0[2], o1[2];
#pragma unroll
        for (int j = 0; j < 2; ++j) { o0[j] = 0ull; o1[j] = 0ull; }
#pragma unroll
        for (int kp = 0; kp < 64; ++kp) {
            const ulonglong2 w = *(const ulonglong2*)&sW2[kp * 128 + lane * 4];
#pragma unroll
            for (int j = 0; j < 2; ++j) {
                const u64 a = *(const u64*)&myT[j * 192 + 64 + kp * 2];
                fma2(o0[j], a, w.x); fma2(o1[j], a, w.y);
            }
        }
#pragma unroll
        for (int j = 0; j < 2; ++j) {
            const int n = base + j;
            if (n < N) {
                const float2 xv = *(const float2*)&myT[j * 192 + lane * 2];
                float2 res;
                res.x = xv.x + psum(o0[j]) + b2v.x;
                res.y = xv.y + psum(o1[j]) + b2v.y;
                *(float2*)&out[(size_t)n * NODE_DIM + lane * 2] = res;
            }
        }
    }
}

// ---------------- host ----------------
extern "C" void kernel_launch(void* const* d_in, const int* in_sizes, int n_in,
                              void* d_out, int out_size) {
    const float* x      = (const float*)d_in[0];
    const int*   ei     = (const int*)  d_in[1];
    const float* ea     = (const float*)d_in[2];
    const float* Wmsg1  = (const float*)d_in[3];
    const float* bmsg1  = (const float*)d_in[4];
    const float* gmsg   = (const float*)d_in[5];
    const float* bemsg  = (const float*)d_in[6];
    const float* Wmsg2  = (const float*)d_in[7];
    const float* bmsg2  = (const float*)d_in[8];
    const float* Wupd1  = (const float*)d_in[9];
    const float* bupd1  = (const float*)d_in[10];
    const float* gupd   = (const float*)d_in[11];
    const float* beupd  = (const float*)d_in[12];
    const float* Wupd2  = (const float*)d_in[13];
    const float* bupd2  = (const float*)d_in[14];
    float* out = (float*)d_out;

    const int N = in_sizes[0] / NODE_DIM;
    const int E = in_sizes[2] / EDGE_DIM;

    void *pS = nullptr, *pdeg = nullptr;
    cudaGetSymbolAddress(&pS, g_S);
    cudaGetSymbolAddress(&pdeg, g_deg);
    cudaMemsetAsync(pS, 0, (size_t)N * HIDDEN * sizeof(float), 0);
    cudaMemsetAsync(pdeg, 0, (size_t)N * sizeof(float), 0);

    const int smem_proj = (8192 + 8192 + 2048) * sizeof(float);                    // 72 KB
    const int smem_upd  = (8192 + 16384 + 8192 + 4 * HIDDEN + NODE_DIM + 6144) * sizeof(float); // ~158 KB
    cudaFuncSetAttribute(k_node_proj, cudaFuncAttributeMaxDynamicSharedMemorySize, smem_proj);
    cudaFuncSetAttribute(k_update,    cudaFuncAttributeMaxDynamicSharedMemorySize, smem_upd);

    // launch order: 4th non-memset kernel = k_edge_lite (ncu capture target)
    k_fuse<<<HIDDEN, HIDDEN>>>(Wmsg2, Wupd1, bmsg2);
    k_node_proj<<<296, 256, smem_proj>>>(x, Wmsg1, bmsg1, N);
    k_eaw<<<1184, 256>>>(ea, Wmsg1, E);
    k_edge_lite<<<1184, 256>>>(ei, gmsg, bemsg, E);
    k_update<<<148, 512, smem_upd>>>(x, Wupd1, bupd1, gupd, beupd, Wupd2, bupd2, out, N);
}

// round 13
// speedup vs baseline: 1.1219x; 1.1219x over previous
#include <cuda_runtime.h>
#include <cuda_bf16.h>

#define NODE_DIM 64
#define EDGE_DIM 32
#define HIDDEN   128
#define MAXN     100000
#define MAXE     800000
#define LN_EPS   1e-5f

typedef unsigned long long u64;

// ---------------- scratch (no allocs allowed) ----------------
__device__ __align__(16) float g_xs[MAXN * HIDDEN];   // x @ W_src
__device__ __align__(16) float g_xd[MAXN * HIDDEN];   // x @ W_dst + b_msg1
__device__ __align__(16) float g_S [MAXN * HIDDEN];   // scatter-sum of edge activations
__device__ __align__(16) float g_deg[MAXN];           // in-degree (float)
__device__ __align__(16) float g_c [HIDDEN];          // b_msg2 @ W_upd1[64:192]
__device__ __align__(16) float g_Wf_p[64 * 128 * 2];  // conflict-free pair layout

// ---------------- helpers ----------------
__device__ __forceinline__ u64 pk(float lo, float hi) {
    u64 r; asm("mov.b64 %0,{%1,%2};" : "=l"(r) : "f"(lo), "f"(hi)); return r;
}
__device__ __forceinline__ void fma2(u64& d, u64 a, u64 b) {
    asm("fma.rn.f32x2 %0,%1,%2,%0;" : "+l"(d) : "l"(a), "l"(b));
}
__device__ __forceinline__ float psum(u64 v) {
    float lo, hi; asm("mov.b64 {%0,%1},%2;" : "=f"(lo), "=f"(hi) : "l"(v));
    return lo + hi;
}
__device__ __forceinline__ float silu_f(float y) {
    return y * (1.0f / (1.0f + __expf(-y)));
}
__device__ __forceinline__ void red_add_v4(float* p, float4 v) {
    asm volatile("red.global.add.v4.f32 [%0], {%1,%2,%3,%4};"
                 :: "l"(p), "f"(v.x), "f"(v.y), "f"(v.z), "f"(v.w) : "memory");
}

// conflict-free pair layout index: W[k][c] -> base[((kp*4+cc)*32 + lane)*2 + h]
__device__ __forceinline__ int pidx(int k, int c) {
    return (((k >> 1) * 4 + (c & 3)) * 32 + (c >> 2)) * 2 + (k & 1);
}

// ---------------- K fuse: Wf = W_msg2 @ W_upd1[64:192] ----------
__global__ void k_fuse(const float* __restrict__ Wmsg2,
                       const float* __restrict__ Wupd1,
                       const float* __restrict__ bmsg2) {
    int k = blockIdx.x;      // 0..127
    int t = threadIdx.x;     // 0..127
    float acc = 0.f;
#pragma unroll 8
    for (int j = 0; j < HIDDEN; ++j)
        acc = fmaf(Wmsg2[k * HIDDEN + j], Wupd1[(NODE_DIM + j) * HIDDEN + t], acc);
    g_Wf_p[pidx(k, t)] = acc;
    if (k == 0) {
        float c = 0.f;
#pragma unroll 8
        for (int j = 0; j < HIDDEN; ++j)
            c = fmaf(bmsg2[j], Wupd1[(NODE_DIM + j) * HIDDEN + t], c);
        g_c[t] = c;
    }
}

// ---------------- K node_proj: xs = x@W_src, xd = x@W_dst + b1 (FFMA2) ----------
__global__ __launch_bounds__(256)
void k_node_proj(const float* __restrict__ x,
                 const float* __restrict__ Wmsg1,
                 const float* __restrict__ b1, int N) {
    extern __shared__ float sm[];
    float* sWs = sm;             // 8192 (pair layout)
    float* sWd = sWs + 8192;     // 8192
    float* sX  = sWd + 8192;     // 8 warps * 4 nodes * 64 = 2048
    for (int i = threadIdx.x; i < 8192; i += blockDim.x) {
        const int k = i >> 7, c = i & 127;
        const int idx = pidx(k, c);
        sWs[idx] = Wmsg1[i];
        sWd[idx] = Wmsg1[8192 + i];
    }
    __syncthreads();
    const int lane = threadIdx.x & 31, warp = threadIdx.x >> 5;
    const int gw = blockIdx.x * 8 + warp;
    const int nwarps = gridDim.x * 8;
    float* myX = &sX[warp * 4 * 64];
    const float4 b1v = *(const float4*)&b1[lane * 4];

    for (int base = gw * 4; base < N; base += nwarps * 4) {
        __syncwarp();
#pragma unroll
        for (int j = 0; j < 4; ++j) {
            const int n = base + j;
            float2 xv = make_float2(0.f, 0.f);
            if (n < N) xv = *(const float2*)&x[n * NODE_DIM + lane * 2];
            *(float2*)&myX[j * 64 + lane * 2] = xv;
        }
        __syncwarp();
        u64 aS[4][4], aD[4][4];
#pragma unroll
        for (int j = 0; j < 4; ++j)
#pragma unroll
            for (int cc = 0; cc < 4; ++cc) { aS[j][cc] = 0ull; aD[j][cc] = 0ull; }
#pragma unroll
        for (int kp = 0; kp < 32; ++kp) {
            u64 ws[4], wd[4];
#pragma unroll
            for (int cc = 0; cc < 4; ++cc) {
                ws[cc] = *(const u64*)&sWs[((kp * 4 + cc) * 32 + lane) * 2];
                wd[cc] = *(const u64*)&sWd[((kp * 4 + cc) * 32 + lane) * 2];
            }
#pragma unroll
            for (int j = 0; j < 4; ++j) {
                const u64 a = *(const u64*)&myX[j * 64 + kp * 2];
                fma2(aS[j][0], a, ws[0]); fma2(aS[j][1], a, ws[1]);
                fma2(aS[j][2], a, ws[2]); fma2(aS[j][3], a, ws[3]);
                fma2(aD[j][0], a, wd[0]); fma2(aD[j][1], a, wd[1]);
                fma2(aD[j][2], a, wd[2]); fma2(aD[j][3], a, wd[3]);
            }
        }
#pragma unroll
        for (int j = 0; j < 4; ++j) {
            const int n = base + j;
            if (n < N) {
                float4 os = make_float4(psum(aS[j][0]), psum(aS[j][1]),
                                        psum(aS[j][2]), psum(aS[j][3]));
                float4 od = make_float4(psum(aD[j][0]) + b1v.x, psum(aD[j][1]) + b1v.y,
                                        psum(aD[j][2]) + b1v.z, psum(aD[j][3]) + b1v.w);
                *(float4*)&g_xs[(size_t)n * HIDDEN + lane * 4] = os;
                *(float4*)&g_xd[(size_t)n * HIDDEN + lane * 4] = od;
            }
        }
    }
}

// ---------------- K edge: warp per 4 edges, scalar FFMA + shuffle (measured best) ------
__global__ __launch_bounds__(256)
void k_edge(const int* __restrict__ ei, const float* __restrict__ ea,
            const float* __restrict__ Wmsg1,
            const float* __restrict__ gm, const float* __restrict__ bem, int E) {
    __shared__ __align__(16) float sWe[EDGE_DIM * HIDDEN]; // rows 128..159 of W_msg1
    __shared__ __align__(16) float sg[HIDDEN];
    __shared__ __align__(16) float sbe[HIDDEN];
    for (int i = threadIdx.x; i < EDGE_DIM * HIDDEN; i += blockDim.x)
        sWe[i] = Wmsg1[HIDDEN * HIDDEN + i];
    for (int i = threadIdx.x; i < HIDDEN; i += blockDim.x) {
        sg[i] = gm[i]; sbe[i] = bem[i];
    }
    __syncthreads();
    const int lane = threadIdx.x & 31, warp = threadIdx.x >> 5;
    const int gw = blockIdx.x * 8 + warp;
    const int nwarps = gridDim.x * 8;
    const float4 gv  = *(const float4*)&sg[lane * 4];
    const float4 bev = *(const float4*)&sbe[lane * 4];

    for (int base = gw * 4; base < E; base += nwarps * 4) {
        int dsts[4];
        float eav[4];
        float4 acc[4];
#pragma unroll
        for (int j = 0; j < 4; ++j) {
            const int e = base + j;
            if (e < E) {
                const int src = ei[e];
                dsts[j] = ei[E + e];
                const float4 vs = *(const float4*)&g_xs[(size_t)src * HIDDEN + lane * 4];
                const float4 vd = *(const float4*)&g_xd[(size_t)dsts[j] * HIDDEN + lane * 4];
                acc[j].x = vs.x + vd.x;
                acc[j].y = vs.y + vd.y;
                acc[j].z = vs.z + vd.z;
                acc[j].w = vs.w + vd.w;
                eav[j] = ea[(size_t)e * EDGE_DIM + lane];
            } else {
                dsts[j] = -1;
                acc[j] = make_float4(0.f, 0.f, 0.f, 0.f);
                eav[j] = 0.f;
            }
        }
#pragma unroll
        for (int k = 0; k < 32; ++k) {
            const float4 w = *(const float4*)&sWe[k * HIDDEN + lane * 4];
#pragma unroll
            for (int j = 0; j < 4; ++j) {
                const float a = __shfl_sync(0xffffffffu, eav[j], k);
                acc[j].x = fmaf(a, w.x, acc[j].x);
                acc[j].y = fmaf(a, w.y, acc[j].y);
                acc[j].z = fmaf(a, w.z, acc[j].z);
                acc[j].w = fmaf(a, w.w, acc[j].w);
            }
        }
#pragma unroll
        for (int j = 0; j < 4; ++j) {
            if (dsts[j] < 0) continue;
            float s1 = acc[j].x + acc[j].y + acc[j].z + acc[j].w;
            float s2 = fmaf(acc[j].x, acc[j].x, fmaf(acc[j].y, acc[j].y,
                       fmaf(acc[j].z, acc[j].z, acc[j].w * acc[j].w)));
#pragma unroll
            for (int o = 16; o > 0; o >>= 1) {
                s1 += __shfl_xor_sync(0xffffffffu, s1, o);
                s2 += __shfl_xor_sync(0xffffffffu, s2, o);
            }
            const float mu = s1 * (1.0f / HIDDEN);
            const float var = fmaf(-mu, mu, s2 * (1.0f / HIDDEN));
            const float rstd = rsqrtf(var + LN_EPS);
            float4 act;
            act.x = silu_f((acc[j].x - mu) * rstd * gv.x + bev.x);
            act.y = silu_f((acc[j].y - mu) * rstd * gv.y + bev.y);
            act.z = silu_f((acc[j].z - mu) * rstd * gv.z + bev.z);
            act.w = silu_f((acc[j].w - mu) * rstd * gv.w + bev.w);
            red_add_v4(&g_S[(size_t)dsts[j] * HIDDEN + lane * 4], act);
            if (lane == 0) atomicAdd(&g_deg[dsts[j]], 1.0f);
        }
    }
}

// ---------------- K update: fused node update (384 thr, warp per 2 nodes, FFMA2) ------
__global__ __launch_bounds__(384, 1)
void k_update(const float* __restrict__ x,
              const float* __restrict__ Wupd1, const float* __restrict__ bupd1,
              const float* __restrict__ gu, const float* __restrict__ beu,
              const float* __restrict__ Wupd2, const float* __restrict__ bupd2,
              float* __restrict__ out, int N) {
    extern __shared__ float sm[];
    float* sWa = sm;                       // 8192  (pair layout)
    float* sWf = sWa + 8192;               // 16384 (pair layout)
    float* sW2 = sWf + 16384;              // 8192  (interleave, conflict-free)
    float* sb1 = sW2 + 8192;               // 128
    float* sc  = sb1 + HIDDEN;             // 128
    float* sg  = sc  + HIDDEN;             // 128
    float* sbe = sg  + HIDDEN;             // 128
    float* sb2 = sbe + HIDDEN;             // 64
    float* sT  = sb2 + NODE_DIM;           // 12 warps * 2 nodes * 192 = 4608
    for (int i = threadIdx.x; i < 8192; i += blockDim.x) {
        const int k = i >> 7, c = i & 127;
        sWa[pidx(k, c)] = Wupd1[i];
        const int k2 = i >> 6, c2 = i & 63;
        sW2[(k2 >> 1) * 128 + c2 * 2 + (k2 & 1)] = Wupd2[i];
    }
    {
        float4* d = (float4*)sWf; const float4* s = (const float4*)g_Wf_p;
        for (int i = threadIdx.x; i < 4096; i += blockDim.x) d[i] = s[i];
    }
    for (int i = threadIdx.x; i < HIDDEN; i += blockDim.x) {
        sb1[i] = bupd1[i]; sc[i] = g_c[i]; sg[i] = gu[i]; sbe[i] = beu[i];
    }
    for (int i = threadIdx.x; i < NODE_DIM; i += blockDim.x) sb2[i] = bupd2[i];
    __syncthreads();

    const int lane = threadIdx.x & 31, warp = threadIdx.x >> 5;
    const int gw = blockIdx.x * 12 + warp;
    const int nwarps = gridDim.x * 12;
    float* myT = &sT[warp * 2 * 192];   // per node: [0..63]=x, [64..191]=S then act

    const float4 b1v = *(const float4*)&sb1[lane * 4];
    const float4 cv  = *(const float4*)&sc [lane * 4];
    const float4 gv  = *(const float4*)&sg [lane * 4];
    const float4 bev = *(const float4*)&sbe[lane * 4];
    const float2 b2v = *(const float2*)&sb2[lane * 2];

    for (int base = gw * 2; base < N; base += nwarps * 2) {
        __syncwarp();
        u64 acc[2][4];
#pragma unroll
        for (int j = 0; j < 2; ++j) {
            const int n = base + j;
            float2 xv = make_float2(0.f, 0.f);
            float4 s4 = make_float4(0.f, 0.f, 0.f, 0.f);
            float dg = 0.f;
            if (n < N) {
                xv = *(const float2*)&x[n * NODE_DIM + lane * 2];
                s4 = *(const float4*)&g_S[(size_t)n * HIDDEN + lane * 4];
                dg = g_deg[n];
            }
            *(float2*)&myT[j * 192 + lane * 2] = xv;
            *(float4*)&myT[j * 192 + 64 + lane * 4] = s4;
            acc[j][0] = pk(fmaf(dg, cv.x, b1v.x), 0.f);
            acc[j][1] = pk(fmaf(dg, cv.y, b1v.y), 0.f);
            acc[j][2] = pk(fmaf(dg, cv.z, b1v.z), 0.f);
            acc[j][3] = pk(fmaf(dg, cv.w, b1v.w), 0.f);
        }
        __syncwarp();
        // loop1: x @ W_upd1[0:64]
#pragma unroll
        for (int kp = 0; kp < 32; ++kp) {
            u64 w[4];
#pragma unroll
            for (int cc = 0; cc < 4; ++cc)
                w[cc] = *(const u64*)&sWa[((kp * 4 + cc) * 32 + lane) * 2];
#pragma unroll
            for (int j = 0; j < 2; ++j) {
                const u64 a = *(const u64*)&myT[j * 192 + kp * 2];
                fma2(acc[j][0], a, w[0]); fma2(acc[j][1], a, w[1]);
                fma2(acc[j][2], a, w[2]); fma2(acc[j][3], a, w[3]);
            }
        }
        // loop2: S @ Wf
#pragma unroll
        for (int kp = 0; kp < 64; ++kp) {
            u64 w[4];
#pragma unroll
            for (int cc = 0; cc < 4; ++cc)
                w[cc] = *(const u64*)&sWf[((kp * 4 + cc) * 32 + lane) * 2];
#pragma unroll
            for (int j = 0; j < 2; ++j) {
                const u64 a = *(const u64*)&myT[j * 192 + 64 + kp * 2];
                fma2(acc[j][0], a, w[0]); fma2(acc[j][1], a, w[1]);
                fma2(acc[j][2], a, w[2]); fma2(acc[j][3], a, w[3]);
            }
        }
        __syncwarp();
        // LayerNorm (one pass) + SiLU, store act into the S slots
#pragma unroll
        for (int j = 0; j < 2; ++j) {
            const float v0 = psum(acc[j][0]), v1 = psum(acc[j][1]);
            const float v2 = psum(acc[j][2]), v3 = psum(acc[j][3]);
            float s1 = v0 + v1 + v2 + v3;
            float s2 = fmaf(v0, v0, fmaf(v1, v1, fmaf(v2, v2, v3 * v3)));
#pragma unroll
            for (int o = 16; o > 0; o >>= 1) {
                s1 += __shfl_xor_sync(0xffffffffu, s1, o);
                s2 += __shfl_xor_sync(0xffffffffu, s2, o);
            }
            const float mu = s1 * (1.0f / HIDDEN);
            const float var = fmaf(-mu, mu, s2 * (1.0f / HIDDEN));
            const float rstd = rsqrtf(var + LN_EPS);
            float4 act;
            act.x = silu_f((v0 - mu) * rstd * gv.x + bev.x);
            act.y = silu_f((v1 - mu) * rstd * gv.y + bev.y);
            act.z = silu_f((v2 - mu) * rstd * gv.z + bev.z);
            act.w = silu_f((v3 - mu) * rstd * gv.w + bev.w);
            *(float4*)&myT[j * 192 + 64 + lane * 4] = act;
        }
        __syncwarp();
        // loop3: act @ W_upd2 (128 -> 64)
        u64 o0[2], o1[2];
#pragma unroll
        for (int j = 0; j < 2; ++j) { o0[j] = 0ull; o1[j] = 0ull; }
#pragma unroll
        for (int kp = 0; kp < 64; ++kp) {
            const ulonglong2 w = *(const ulonglong2*)&sW2[kp * 128 + lane * 4];
#pragma unroll
            for (int j = 0; j < 2; ++j) {
                const u64 a = *(const u64*)&myT[j * 192 + 64 + kp * 2];
                fma2(o0[j], a, w.x); fma2(o1[j], a, w.y);
            }
        }
#pragma unroll
        for (int j = 0; j < 2; ++j) {
            const int n = base + j;
            if (n < N) {
                const float2 xv = *(const float2*)&myT[j * 192 + lane * 2];
                float2 res;
                res.x = xv.x + psum(o0[j]) + b2v.x;
                res.y = xv.y + psum(o1[j]) + b2v.y;
                *(float2*)&out[(size_t)n * NODE_DIM + lane * 2] = res;
            }
        }
    }
}

// ---------------- host ----------------
extern "C" void kernel_launch(void* const* d_in, const int* in_sizes, int n_in,
                              void* d_out, int out_size) {
    const float* x      = (const float*)d_in[0];
    const int*   ei     = (const int*)  d_in[1];
    const float* ea     = (const float*)d_in[2];
    const float* Wmsg1  = (const float*)d_in[3];
    const float* bmsg1  = (const float*)d_in[4];
    const float* gmsg   = (const float*)d_in[5];
    const float* bemsg  = (const float*)d_in[6];
    const float* Wmsg2  = (const float*)d_in[7];
    const float* bmsg2  = (const float*)d_in[8];
    const float* Wupd1  = (const float*)d_in[9];
    const float* bupd1  = (const float*)d_in[10];
    const float* gupd   = (const float*)d_in[11];
    const float* beupd  = (const float*)d_in[12];
    const float* Wupd2  = (const float*)d_in[13];
    const float* bupd2  = (const float*)d_in[14];
    float* out = (float*)d_out;

    const int N = in_sizes[0] / NODE_DIM;
    const int E = in_sizes[2] / EDGE_DIM;

    void *pS = nullptr, *pdeg = nullptr;
    cudaGetSymbolAddress(&pS, g_S);
    cudaGetSymbolAddress(&pdeg, g_deg);
    cudaMemsetAsync(pS, 0, (size_t)N * HIDDEN * sizeof(float), 0);
    cudaMemsetAsync(pdeg, 0, (size_t)N * sizeof(float), 0);

    const int smem_proj = (8192 + 8192 + 2048) * sizeof(float);                    // 72 KB
    const int smem_upd  = (8192 + 16384 + 8192 + 4 * HIDDEN + NODE_DIM + 4608) * sizeof(float); // ~150 KB
    cudaFuncSetAttribute(k_node_proj, cudaFuncAttributeMaxDynamicSharedMemorySize, smem_proj);
    cudaFuncSetAttribute(k_update,    cudaFuncAttributeMaxDynamicSharedMemorySize, smem_upd);

    // launch order: 4th non-memset kernel = k_update (ncu capture target)
    k_fuse<<<HIDDEN, HIDDEN>>>(Wmsg2, Wupd1, bmsg2);
    k_node_proj<<<296, 256, smem_proj>>>(x, Wmsg1, bmsg1, N);
    k_edge<<<1184, 256>>>(ei, ea, Wmsg1, gmsg, bemsg, E);
    k_update<<<148, 384, smem_upd>>>(x, Wupd1, bupd1, gupd, beupd, Wupd2, bupd2, out, N);
}

// round 14
// speedup vs baseline: 1.1891x; 1.0600x over previous
#include <cuda_runtime.h>
#include <cuda_bf16.h>

#define NODE_DIM 64
#define EDGE_DIM 32
#define HIDDEN   128
#define MAXN     100000
#define MAXE     800000
#define LN_EPS   1e-5f

typedef unsigned long long u64;

// ---------------- scratch (no allocs allowed) ----------------
__device__ __align__(16) float g_xs[MAXN * HIDDEN];   // x @ W_src
__device__ __align__(16) float g_xd[MAXN * HIDDEN];   // x @ W_dst + b_msg1
__device__ __align__(16) float g_S [MAXN * HIDDEN];   // scatter-sum of edge activations
__device__ __align__(16) float g_deg[MAXN];           // in-degree (float)
__device__ __align__(16) float g_c [HIDDEN];          // b_msg2 @ W_upd1[64:192]
__device__ __align__(16) float g_Wf_p[64 * 128 * 2];  // conflict-free pair layout

// ---------------- helpers ----------------
__device__ __forceinline__ u64 pk(float lo, float hi) {
    u64 r; asm("mov.b64 %0,{%1,%2};" : "=l"(r) : "f"(lo), "f"(hi)); return r;
}
__device__ __forceinline__ u64 dup2(float a) {
    u64 r; asm("mov.b64 %0,{%1,%1};" : "=l"(r) : "f"(a)); return r;
}
__device__ __forceinline__ void fma2(u64& d, u64 a, u64 b) {
    asm("fma.rn.f32x2 %0,%1,%2,%0;" : "+l"(d) : "l"(a), "l"(b));
}
__device__ __forceinline__ float psum(u64 v) {
    float lo, hi; asm("mov.b64 {%0,%1},%2;" : "=f"(lo), "=f"(hi) : "l"(v));
    return lo + hi;
}
__device__ __forceinline__ void unpk(u64 v, float& lo, float& hi) {
    asm("mov.b64 {%0,%1},%2;" : "=f"(lo), "=f"(hi) : "l"(v));
}
__device__ __forceinline__ float silu_f(float y) {
    return y * (1.0f / (1.0f + __expf(-y)));
}
__device__ __forceinline__ void red_add_v4(float* p, float4 v) {
    asm volatile("red.global.add.v4.f32 [%0], {%1,%2,%3,%4};"
                 :: "l"(p), "f"(v.x), "f"(v.y), "f"(v.z), "f"(v.w) : "memory");
}

// conflict-free pair layout index: W[k][c] -> base[((kp*4+cc)*32 + lane)*2 + h]
__device__ __forceinline__ int pidx(int k, int c) {
    return (((k >> 1) * 4 + (c & 3)) * 32 + (c >> 2)) * 2 + (k & 1);
}

// ---------------- K fuse: Wf = W_msg2 @ W_upd1[64:192] ----------
__global__ void k_fuse(const float* __restrict__ Wmsg2,
                       const float* __restrict__ Wupd1,
                       const float* __restrict__ bmsg2) {
    int k = blockIdx.x;      // 0..127
    int t = threadIdx.x;     // 0..127
    float acc = 0.f;
#pragma unroll 8
    for (int j = 0; j < HIDDEN; ++j)
        acc = fmaf(Wmsg2[k * HIDDEN + j], Wupd1[(NODE_DIM + j) * HIDDEN + t], acc);
    g_Wf_p[pidx(k, t)] = acc;
    if (k == 0) {
        float c = 0.f;
#pragma unroll 8
        for (int j = 0; j < HIDDEN; ++j)
            c = fmaf(bmsg2[j], Wupd1[(NODE_DIM + j) * HIDDEN + t], c);
        g_c[t] = c;
    }
}

// ---------------- no-op spacer (aligns ncu's 4th-launch capture onto k_edge) ------
__global__ void k_nop() {}

// ---------------- K node_proj: xs = x@W_src, xd = x@W_dst + b1 (FFMA2) ----------
__global__ __launch_bounds__(256)
void k_node_proj(const float* __restrict__ x,
                 const float* __restrict__ Wmsg1,
                 const float* __restrict__ b1, int N) {
    extern __shared__ float sm[];
    float* sWs = sm;             // 8192 (pair layout)
    float* sWd = sWs + 8192;     // 8192
    float* sX  = sWd + 8192;     // 8 warps * 4 nodes * 64 = 2048
    for (int i = threadIdx.x; i < 8192; i += blockDim.x) {
        const int k = i >> 7, c = i & 127;
        const int idx = pidx(k, c);
        sWs[idx] = Wmsg1[i];
        sWd[idx] = Wmsg1[8192 + i];
    }
    __syncthreads();
    const int lane = threadIdx.x & 31, warp = threadIdx.x >> 5;
    const int gw = blockIdx.x * 8 + warp;
    const int nwarps = gridDim.x * 8;
    float* myX = &sX[warp * 4 * 64];
    const float4 b1v = *(const float4*)&b1[lane * 4];

    for (int base = gw * 4; base < N; base += nwarps * 4) {
        __syncwarp();
#pragma unroll
        for (int j = 0; j < 4; ++j) {
            const int n = base + j;
            float2 xv = make_float2(0.f, 0.f);
            if (n < N) xv = *(const float2*)&x[n * NODE_DIM + lane * 2];
            *(float2*)&myX[j * 64 + lane * 2] = xv;
        }
        __syncwarp();
        u64 aS[4][4], aD[4][4];
#pragma unroll
        for (int j = 0; j < 4; ++j)
#pragma unroll
            for (int cc = 0; cc < 4; ++cc) { aS[j][cc] = 0ull; aD[j][cc] = 0ull; }
#pragma unroll
        for (int kp = 0; kp < 32; ++kp) {
            u64 ws[4], wd[4];
#pragma unroll
            for (int cc = 0; cc < 4; ++cc) {
                ws[cc] = *(const u64*)&sWs[((kp * 4 + cc) * 32 + lane) * 2];
                wd[cc] = *(const u64*)&sWd[((kp * 4 + cc) * 32 + lane) * 2];
            }
#pragma unroll
            for (int j = 0; j < 4; ++j) {
                const u64 a = *(const u64*)&myX[j * 64 + kp * 2];
                fma2(aS[j][0], a, ws[0]); fma2(aS[j][1], a, ws[1]);
                fma2(aS[j][2], a, ws[2]); fma2(aS[j][3], a, ws[3]);
                fma2(aD[j][0], a, wd[0]); fma2(aD[j][1], a, wd[1]);
                fma2(aD[j][2], a, wd[2]); fma2(aD[j][3], a, wd[3]);
            }
        }
#pragma unroll
        for (int j = 0; j < 4; ++j) {
            const int n = base + j;
            if (n < N) {
                float4 os = make_float4(psum(aS[j][0]), psum(aS[j][1]),
                                        psum(aS[j][2]), psum(aS[j][3]));
                float4 od = make_float4(psum(aD[j][0]) + b1v.x, psum(aD[j][1]) + b1v.y,
                                        psum(aD[j][2]) + b1v.z, psum(aD[j][3]) + b1v.w);
                *(float4*)&g_xs[(size_t)n * HIDDEN + lane * 4] = os;
                *(float4*)&g_xd[(size_t)n * HIDDEN + lane * 4] = od;
            }
        }
    }
}

// ---------------- K edge: warp per 4 edges, col-pair FFMA2 + shuffle ------
__global__ __launch_bounds__(256)
void k_edge(const int* __restrict__ ei, const float* __restrict__ ea,
            const float* __restrict__ Wmsg1,
            const float* __restrict__ gm, const float* __restrict__ bem, int E) {
    __shared__ __align__(16) float sWe[EDGE_DIM * HIDDEN]; // rows 128..159, row-major
    __shared__ __align__(16) float sg[HIDDEN];
    __shared__ __align__(16) float sbe[HIDDEN];
    for (int i = threadIdx.x; i < EDGE_DIM * HIDDEN; i += blockDim.x)
        sWe[i] = Wmsg1[HIDDEN * HIDDEN + i];
    for (int i = threadIdx.x; i < HIDDEN; i += blockDim.x) {
        sg[i] = gm[i]; sbe[i] = bem[i];
    }
    __syncthreads();
    const int lane = threadIdx.x & 31, warp = threadIdx.x >> 5;
    const int gw = blockIdx.x * 8 + warp;
    const int nwarps = gridDim.x * 8;
    const float4 gv  = *(const float4*)&sg[lane * 4];
    const float4 bev = *(const float4*)&sbe[lane * 4];

    for (int base = gw * 4; base < E; base += nwarps * 4) {
        int dsts[4];
        float eav[4];
        u64 acc[4][2];   // (col0,col1),(col2,col3) as f32x2
#pragma unroll
        for (int j = 0; j < 4; ++j) {
            const int e = base + j;
            if (e < E) {
                const int src = ei[e];
                dsts[j] = ei[E + e];
                const float4 vs = *(const float4*)&g_xs[(size_t)src * HIDDEN + lane * 4];
                const float4 vd = *(const float4*)&g_xd[(size_t)dsts[j] * HIDDEN + lane * 4];
                acc[j][0] = pk(vs.x + vd.x, vs.y + vd.y);
                acc[j][1] = pk(vs.z + vd.z, vs.w + vd.w);
                eav[j] = ea[(size_t)e * EDGE_DIM + lane];
            } else {
                dsts[j] = -1;
                acc[j][0] = 0ull; acc[j][1] = 0ull;
                eav[j] = 0.f;
            }
        }
#pragma unroll
        for (int k = 0; k < 32; ++k) {
            const ulonglong2 w = *(const ulonglong2*)&sWe[k * HIDDEN + lane * 4];
#pragma unroll
            for (int j = 0; j < 4; ++j) {
                const u64 a2 = dup2(__shfl_sync(0xffffffffu, eav[j], k));
                fma2(acc[j][0], a2, w.x);
                fma2(acc[j][1], a2, w.y);
            }
        }
#pragma unroll
        for (int j = 0; j < 4; ++j) {
            if (dsts[j] < 0) continue;
            float v0, v1, v2, v3;
            unpk(acc[j][0], v0, v1);
            unpk(acc[j][1], v2, v3);
            float s1 = v0 + v1 + v2 + v3;
            float s2 = fmaf(v0, v0, fmaf(v1, v1, fmaf(v2, v2, v3 * v3)));
#pragma unroll
            for (int o = 16; o > 0; o >>= 1) {
                s1 += __shfl_xor_sync(0xffffffffu, s1, o);
                s2 += __shfl_xor_sync(0xffffffffu, s2, o);
            }
            const float mu = s1 * (1.0f / HIDDEN);
            const float var = fmaf(-mu, mu, s2 * (1.0f / HIDDEN));
            const float rstd = rsqrtf(var + LN_EPS);
            float4 act;
            act.x = silu_f((v0 - mu) * rstd * gv.x + bev.x);
            act.y = silu_f((v1 - mu) * rstd * gv.y + bev.y);
            act.z = silu_f((v2 - mu) * rstd * gv.z + bev.z);
            act.w = silu_f((v3 - mu) * rstd * gv.w + bev.w);
            red_add_v4(&g_S[(size_t)dsts[j] * HIDDEN + lane * 4], act);
            if (lane == 0) atomicAdd(&g_deg[dsts[j]], 1.0f);
        }
    }
}

// ---------------- K update: fused node update (256 thr, warp per 4 nodes, FFMA2) ------
__global__ __launch_bounds__(256, 1)
void k_update(const float* __restrict__ x,
              const float* __restrict__ Wupd1, const float* __restrict__ bupd1,
              const float* __restrict__ gu, const float* __restrict__ beu,
              const float* __restrict__ Wupd2, const float* __restrict__ bupd2,
              float* __restrict__ out, int N) {
    extern __shared__ float sm[];
    float* sWa = sm;                       // 8192  (pair layout)
    float* sWf = sWa + 8192;               // 16384 (pair layout)
    float* sW2 = sWf + 16384;              // 8192  (interleave, conflict-free)
    float* sb1 = sW2 + 8192;               // 128
    float* sc  = sb1 + HIDDEN;             // 128
    float* sg  = sc  + HIDDEN;             // 128
    float* sbe = sg  + HIDDEN;             // 128
    float* sb2 = sbe + HIDDEN;             // 64
    float* sT  = sb2 + NODE_DIM;           // 8 warps * 4 nodes * 192 = 6144
    for (int i = threadIdx.x; i < 8192; i += blockDim.x) {
        const int k = i >> 7, c = i & 127;
        sWa[pidx(k, c)] = Wupd1[i];
        const int k2 = i >> 6, c2 = i & 63;
        sW2[(k2 >> 1) * 128 + c2 * 2 + (k2 & 1)] = Wupd2[i];
    }
    {
        float4* d = (float4*)sWf; const float4* s = (const float4*)g_Wf_p;
        for (int i = threadIdx.x; i < 4096; i += blockDim.x) d[i] = s[i];
    }
    for (int i = threadIdx.x; i < HIDDEN; i += blockDim.x) {
        sb1[i] = bupd1[i]; sc[i] = g_c[i]; sg[i] = gu[i]; sbe[i] = beu[i];
    }
    for (int i = threadIdx.x; i < NODE_DIM; i += blockDim.x) sb2[i] = bupd2[i];
    __syncthreads();

    const int lane = threadIdx.x & 31, warp = threadIdx.x >> 5;
    const int gw = blockIdx.x * 8 + warp;
    const int nwarps = gridDim.x * 8;
    float* myT = &sT[warp * 4 * 192];   // per node: [0..63]=x, [64..191]=S then act

    const float4 b1v = *(const float4*)&sb1[lane * 4];
    const float4 cv  = *(const float4*)&sc [lane * 4];
    const float4 gv  = *(const float4*)&sg [lane * 4];
    const float4 bev = *(const float4*)&sbe[lane * 4];
    const float2 b2v = *(const float2*)&sb2[lane * 2];

    for (int base = gw * 4; base < N; base += nwarps * 4) {
        __syncwarp();
        u64 acc[4][4];
#pragma unroll
        for (int j = 0; j < 4; ++j) {
            const int n = base + j;
            float2 xv = make_float2(0.f, 0.f);
            float4 s4 = make_float4(0.f, 0.f, 0.f, 0.f);
            float dg = 0.f;
            if (n < N) {
                xv = *(const float2*)&x[n * NODE_DIM + lane * 2];
                s4 = *(const float4*)&g_S[(size_t)n * HIDDEN + lane * 4];
                dg = g_deg[n];
            }
            *(float2*)&myT[j * 192 + lane * 2] = xv;
            *(float4*)&myT[j * 192 + 64 + lane * 4] = s4;
            acc[j][0] = pk(fmaf(dg, cv.x, b1v.x), 0.f);
            acc[j][1] = pk(fmaf(dg, cv.y, b1v.y), 0.f);
            acc[j][2] = pk(fmaf(dg, cv.z, b1v.z), 0.f);
            acc[j][3] = pk(fmaf(dg, cv.w, b1v.w), 0.f);
        }
        __syncwarp();
        // loop1: x @ W_upd1[0:64]
#pragma unroll
        for (int kp = 0; kp < 32; ++kp) {
            u64 w[4];
#pragma unroll
            for (int cc = 0; cc < 4; ++cc)
                w[cc] = *(const u64*)&sWa[((kp * 4 + cc) * 32 + lane) * 2];
#pragma unroll
            for (int j = 0; j < 4; ++j) {
                const u64 a = *(const u64*)&myT[j * 192 + kp * 2];
                fma2(acc[j][0], a, w[0]); fma2(acc[j][1], a, w[1]);
                fma2(acc[j][2], a, w[2]); fma2(acc[j][3], a, w[3]);
            }
        }
        // loop2: S @ Wf
#pragma unroll
        for (int kp = 0; kp < 64; ++kp) {
            u64 w[4];
#pragma unroll
            for (int cc = 0; cc < 4; ++cc)
                w[cc] = *(const u64*)&sWf[((kp * 4 + cc) * 32 + lane) * 2];
#pragma unroll
            for (int j = 0; j < 4; ++j) {
                const u64 a = *(const u64*)&myT[j * 192 + 64 + kp * 2];
                fma2(acc[j][0], a, w[0]); fma2(acc[j][1], a, w[1]);
                fma2(acc[j][2], a, w[2]); fma2(acc[j][3], a, w[3]);
            }
        }
        __syncwarp();
        // LayerNorm (one pass) + SiLU, store act into the S slots
#pragma unroll
        for (int j = 0; j < 4; ++j) {
            const float v0 = psum(acc[j][0]), v1 = psum(acc[j][1]);
            const float v2 = psum(acc[j][2]), v3 = psum(acc[j][3]);
            float s1 = v0 + v1 + v2 + v3;
            float s2 = fmaf(v0, v0, fmaf(v1, v1, fmaf(v2, v2, v3 * v3)));
#pragma unroll
            for (int o = 16; o > 0; o >>= 1) {
                s1 += __shfl_xor_sync(0xffffffffu, s1, o);
                s2 += __shfl_xor_sync(0xffffffffu, s2, o);
            }
            const float mu = s1 * (1.0f / HIDDEN);
            const float var = fmaf(-mu, mu, s2 * (1.0f / HIDDEN));
            const float rstd = rsqrtf(var + LN_EPS);
            float4 act;
            act.x = silu_f((v0 - mu) * rstd * gv.x + bev.x);
            act.y = silu_f((v1 - mu) * rstd * gv.y + bev.y);
            act.z = silu_f((v2 - mu) * rstd * gv.z + bev.z);
            act.w = silu_f((v3 - mu) * rstd * gv.w + bev.w);
            *(float4*)&myT[j * 192 + 64 + lane * 4] = act;
        }
        __syncwarp();
        // loop3: act @ W_upd2 (128 -> 64)
        u64 o0[4], o1[4];
#pragma unroll
        for (int j = 0; j < 4; ++j) { o0[j] = 0ull; o1[j] = 0ull; }
#pragma unroll
        for (int kp = 0; kp < 64; ++kp) {
            const ulonglong2 w = *(const ulonglong2*)&sW2[kp * 128 + lane * 4];
#pragma unroll
            for (int j = 0; j < 4; ++j) {
                const u64 a = *(const u64*)&myT[j * 192 + 64 + kp * 2];
                fma2(o0[j], a, w.x); fma2(o1[j], a, w.y);
            }
        }
#pragma unroll
        for (int j = 0; j < 4; ++j) {
            const int n = base + j;
            if (n < N) {
                const float2 xv = *(const float2*)&myT[j * 192 + lane * 2];
                float2 res;
                res.x = xv.x + psum(o0[j]) + b2v.x;
                res.y = xv.y + psum(o1[j]) + b2v.y;
                *(float2*)&out[(size_t)n * NODE_DIM + lane * 2] = res;
            }
        }
    }
}

// ---------------- host ----------------
extern "C" void kernel_launch(void* const* d_in, const int* in_sizes, int n_in,
                              void* d_out, int out_size) {
    const float* x      = (const float*)d_in[0];
    const int*   ei     = (const int*)  d_in[1];
    const float* ea     = (const float*)d_in[2];
    const float* Wmsg1  = (const float*)d_in[3];
    const float* bmsg1  = (const float*)d_in[4];
    const float* gmsg   = (const float*)d_in[5];
    const float* bemsg  = (const float*)d_in[6];
    const float* Wmsg2  = (const float*)d_in[7];
    const float* bmsg2  = (const float*)d_in[8];
    const float* Wupd1  = (const float*)d_in[9];
    const float* bupd1  = (const float*)d_in[10];
    const float* gupd   = (const float*)d_in[11];
    const float* beupd  = (const float*)d_in[12];
    const float* Wupd2  = (const float*)d_in[13];
    const float* bupd2  = (const float*)d_in[14];
    float* out = (float*)d_out;

    const int N = in_sizes[0] / NODE_DIM;
    const int E = in_sizes[2] / EDGE_DIM;

    void *pS = nullptr, *pdeg = nullptr;
    cudaGetSymbolAddress(&pS, g_S);
    cudaGetSymbolAddress(&pdeg, g_deg);
    cudaMemsetAsync(pS, 0, (size_t)N * HIDDEN * sizeof(float), 0);
    cudaMemsetAsync(pdeg, 0, (size_t)N * sizeof(float), 0);

    const int smem_proj = (8192 + 8192 + 2048) * sizeof(float);                    // 72 KB
    const int smem_upd  = (8192 + 16384 + 8192 + 4 * HIDDEN + NODE_DIM + 6144) * sizeof(float); // ~158 KB
    cudaFuncSetAttribute(k_node_proj, cudaFuncAttributeMaxDynamicSharedMemorySize, smem_proj);
    cudaFuncSetAttribute(k_update,    cudaFuncAttributeMaxDynamicSharedMemorySize, smem_upd);

    // launch order: 4th non-memset kernel = k_edge (ncu capture target)
    k_fuse<<<HIDDEN, HIDDEN>>>(Wmsg2, Wupd1, bmsg2);
    k_node_proj<<<296, 256, smem_proj>>>(x, Wmsg1, bmsg1, N);
    k_nop<<<1, 32>>>();
    k_edge<<<1184, 256>>>(ei, ea, Wmsg1, gmsg, bemsg, E);
    k_update<<<148, 256, smem_upd>>>(x, Wupd1, bupd1, gupd, beupd, Wupd2, bupd2, out, N);
}